// round 15
// baseline (speedup 1.0000x reference)
#include <cuda_runtime.h>
#include <cuda_fp16.h>
#include <cstdint>

// Problem dims (fixed)
#define N_TOK   8192
#define D_IN    2048
#define D_OUT   8192

// Tiling
#define BM      128
#define BN      128
#define BK      128
#define NITER   (D_IN / BK)          // 16
#define STAGES  2
#define THREADS 256

#define A_TILE_B  32768
#define W_TILE_B  65536
#define STG_B     (A_TILE_B + W_TILE_B)      // 98304
#define HALF_B    (STG_B / 2)                // 49152
#define SMEM_BYTES (1024 + STAGES * STG_B)   // 197632

#define NUM_MT  (N_TOK / BM)         // 64
#define NUM_NT  (D_OUT / BN)         // 64
#define NUM_KT  (D_IN / BK)          // 16
#define N_TILES (NUM_MT * NUM_NT)    // 4096

__device__ __align__(1024) char g_xh[(size_t)NUM_MT * NUM_KT * A_TILE_B];
__device__ __align__(1024) char g_wh[(size_t)NUM_NT * NUM_KT * W_TILE_B];

__device__ __forceinline__ uint32_t smem_u32(const void* p) {
    uint32_t a;
    asm("{ .reg .u64 t; cvta.to.shared.u64 t, %1; cvt.u32.u64 %0, t; }" : "=r"(a) : "l"(p));
    return a;
}
__device__ __forceinline__ uint32_t swz(uint32_t off) {
    return off ^ ((off >> 3) & 0x70);
}
__device__ __forceinline__ void ldsm4(uint32_t* r, uint32_t addr) {
    asm volatile("ldmatrix.sync.aligned.m8n8.x4.shared.b16 {%0,%1,%2,%3}, [%4];"
                 : "=r"(r[0]), "=r"(r[1]), "=r"(r[2]), "=r"(r[3]) : "r"(addr));
}
__device__ __forceinline__ void mma16816(float* c, const uint32_t* a,
                                         uint32_t b0, uint32_t b1) {
    asm volatile(
        "mma.sync.aligned.m16n8k16.row.col.f32.f16.f16.f32 "
        "{%0,%1,%2,%3}, {%4,%5,%6,%7}, {%8,%9}, {%0,%1,%2,%3};"
        : "+f"(c[0]), "+f"(c[1]), "+f"(c[2]), "+f"(c[3])
        : "r"(a[0]), "r"(a[1]), "r"(a[2]), "r"(a[3]), "r"(b0), "r"(b1));
}
__device__ __forceinline__ void mbar_init(uint32_t a, uint32_t cnt) {
    asm volatile("mbarrier.init.shared.b64 [%0], %1;" :: "r"(a), "r"(cnt) : "memory");
}
__device__ __forceinline__ void mbar_arrive(uint32_t a) {
    asm volatile("mbarrier.arrive.shared.b64 _, [%0];" :: "r"(a) : "memory");
}
__device__ __forceinline__ void mbar_expect_tx(uint32_t a, uint32_t bytes) {
    asm volatile("mbarrier.arrive.expect_tx.shared.b64 _, [%0], %1;"
                 :: "r"(a), "r"(bytes) : "memory");
}
__device__ __forceinline__ void mbar_wait(uint32_t a, uint32_t parity) {
    asm volatile(
        "{\n\t.reg .pred P;\n\t"
        "WL_%=:\n\t"
        "mbarrier.try_wait.parity.acquire.cta.shared::cta.b64 P, [%0], %1, 0x989680;\n\t"
        "@P bra.uni WD_%=;\n\t"
        "bra.uni WL_%=;\n\t"
        "WD_%=:\n\t}"
        :: "r"(a), "r"(parity) : "memory");
}
__device__ __forceinline__ void bulk_ld(uint32_t sdst, const void* gsrc,
                                        uint32_t bytes, uint32_t mbar) {
    asm volatile(
        "cp.async.bulk.shared::cluster.global.mbarrier::complete_tx::bytes "
        "[%0], [%1], %2, [%3];"
        :: "r"(sdst), "l"(gsrc), "r"(bytes), "r"(mbar) : "memory");
}

// ---------------------------------------------------------------------------
// Fused prep (R13-verified mappings)
// ---------------------------------------------------------------------------
#define PREP_XB   2048
#define PREP_WB   4096
__global__ void prep_all(const float* __restrict__ x,
                         const float* __restrict__ mu,
                         const float* __restrict__ sigma,
                         char* __restrict__ dx, char* __restrict__ dw) {
    if (blockIdx.x < PREP_XB) {
        const int total = NUM_MT * 32 * 1024;
        int id = blockIdx.x * blockDim.x + threadIdx.x;
        int stride = PREP_XB * blockDim.x;
        for (; id < total; id += stride) {
            int t = id >> 10;
            uint32_t w = (id & 1023) * 16;
            uint32_t u = swz(w);
            int r = u >> 7, c = (u >> 4) & 7;
            int mt = t >> 5, kt = t & 31;
            const float* src = x + (size_t)(mt * 128 + r) * D_IN + kt * 64 + c * 8;
            float4 a = *reinterpret_cast<const float4*>(src);
            float4 b = *reinterpret_cast<const float4*>(src + 4);
            __half o[8] = { __float2half_rn(a.x), __float2half_rn(a.y),
                            __float2half_rn(a.z), __float2half_rn(a.w),
                            __float2half_rn(b.x), __float2half_rn(b.y),
                            __float2half_rn(b.z), __float2half_rn(b.w) };
            *reinterpret_cast<uint4*>(dx + (size_t)id * 16) = *reinterpret_cast<uint4*>(o);
        }
    } else {
        const int total = NUM_NT * 32 * 1024;
        int id = (blockIdx.x - PREP_XB) * blockDim.x + threadIdx.x;
        int stride = PREP_WB * blockDim.x;
        for (; id < total; id += stride) {
            int t = id >> 10;
            uint32_t w = (id & 1023) * 16;
            uint32_t u = swz(w);
            int r = u >> 7, c = (u >> 4) & 7;
            int nt = t >> 5;
            int kt64 = t & 31;
            int kt128 = kt64 >> 1, kh = kt64 & 1;
            const size_t so = (size_t)(nt * 128 + r) * D_IN + kt64 * 64 + c * 8;
            float4 a = *reinterpret_cast<const float4*>(mu + so);
            float4 b = *reinterpret_cast<const float4*>(mu + so + 4);
            float4 sa = *reinterpret_cast<const float4*>(sigma + so);
            float4 sb = *reinterpret_cast<const float4*>(sigma + so + 4);
            float m[8] = { a.x, a.y, a.z, a.w, b.x, b.y, b.z, b.w };
            float sg[8] = { sa.x, sa.y, sa.z, sa.w, sb.x, sb.y, sb.z, sb.w };
            __half ok[8], om[8];
            #pragma unroll
            for (int q = 0; q < 8; q++) {
                float sp = (sg[q] > 20.f) ? sg[q] : log1pf(expf(sg[q]));
                ok[q] = __float2half_rn(m[q] * sp);
                om[q] = __float2half_rn(m[q]);
            }
            char* tb = dw + ((size_t)nt * NUM_KT + kt128) * W_TILE_B + kh * 16384;
            *reinterpret_cast<uint4*>(tb + w)         = *reinterpret_cast<uint4*>(ok);
            *reinterpret_cast<uint4*>(tb + 32768 + w) = *reinterpret_cast<uint4*>(om);
        }
    }
}

// ---------------------------------------------------------------------------
// Persistent fused dual GEMM: split-half full barriers.
// ctrl layout per stage s (stride 32B): fullH0 = sb+s*32, fullH1 = +8, empty = +16
// ---------------------------------------------------------------------------
__global__ void __launch_bounds__(THREADS, 1)
sbl_gemm_pers(const char* __restrict__ gA,
              const char* __restrict__ gW,
              const float* __restrict__ gate,
              const float* __restrict__ bias,
              float* __restrict__ o_final,
              float* __restrict__ o_scores,
              float* __restrict__ o_output) {
    extern __shared__ char smem[];
    const uint32_t sb = smem_u32(smem);
    const int tid = threadIdx.x;
    const int warp = tid >> 5;
    const int lane = tid & 31;
    const int wm = warp >> 2;
    const int wn = warp & 3;

    if (tid == 0) {
        #pragma unroll
        for (int s = 0; s < STAGES; s++) {
            mbar_init(sb + s * 32, 1);        // fullH0
            mbar_init(sb + s * 32 + 8, 1);    // fullH1
            mbar_init(sb + s * 32 + 16, 8);   // empty
        }
    }
    __syncthreads();

    const uint32_t stg0 = sb + 1024;
    const uint32_t stg1 = sb + 1024 + STG_B;

    const int lr = lane & 15;
    const int lc = lane >> 4;
    uint32_t abase[4], bkb[2], bmb[2];
    #pragma unroll
    for (int mf = 0; mf < 4; mf++)
        abase[mf] = swz((wm * 64 + mf * 16 + lr) * 128 + lc * 16);
    #pragma unroll
    for (int g = 0; g < 2; g++) {
        uint32_t o = swz((wn * 32 + g * 16 + lr) * 128 + lc * 16);
        bkb[g] = A_TILE_B + o;
        bmb[g] = A_TILE_B + 32768 + o;
    }

    uint32_t afr[2][4][4], bkf[2][2][4], bmf[2][2][4];

    auto load_frags = [&](int buf, uint32_t st, int kk) {
        const uint32_t kh = (uint32_t)(kk >> 2) << 14;
        const uint32_t kx = (uint32_t)(kk & 3) << 5;
        #pragma unroll
        for (int mf = 0; mf < 4; mf++)
            ldsm4(afr[buf][mf], st + kh + (abase[mf] ^ kx));
        #pragma unroll
        for (int g = 0; g < 2; g++) {
            ldsm4(bkf[buf][g], st + kh + (bkb[g] ^ kx));
            ldsm4(bmf[buf][g], st + kh + (bmb[g] ^ kx));
        }
    };

    // fill: wait empty, then post expect_tx per half + 3 bulk copies per half
    auto fill = [&](const char* Ab, const char* Wb, int kt) {
        const int s = kt & 1;
        mbar_wait(sb + s * 32 + 16, ((kt >> 1) & 1) ^ 1);
        const uint32_t fH0 = sb + s * 32;
        const uint32_t fH1 = sb + s * 32 + 8;
        mbar_expect_tx(fH0, HALF_B);
        mbar_expect_tx(fH1, HALF_B);
        const uint32_t st = s ? stg1 : stg0;
        const char* As = Ab + (size_t)kt * A_TILE_B;
        const char* Ws = Wb + (size_t)kt * W_TILE_B;
        // half 0: A sub0, keys sub0, mu sub0
        bulk_ld(st,               As,               16384, fH0);
        bulk_ld(st + 32768,       Ws,               16384, fH0);
        bulk_ld(st + 65536,       Ws + 32768,       16384, fH0);
        // half 1: A sub1, keys sub1, mu sub1
        bulk_ld(st + 16384,       As + 16384,       16384, fH1);
        bulk_ld(st + 49152,       Ws + 16384,       16384, fH1);
        bulk_ld(st + 81920,       Ws + 49152,       16384, fH1);
    };

    const int grid = gridDim.x;
    const float scale = 0.022097086912079608f;   // 1/sqrt(2048)

    bool first = true;
    for (int t = blockIdx.x; t < N_TILES; t += grid) {
        const int GM = 8;
        int group = t / (GM * NUM_NT);
        int within = t % (GM * NUM_NT);
        const int m_idx = group * GM + (within % GM);
        const int n_idx = within / GM;
        const int m_base = m_idx * BM;
        const int n_base = n_idx * BN;
        const char* Abase = gA + (size_t)m_idx * NUM_KT * A_TILE_B;
        const char* Wbase = gW + (size_t)n_idx * NUM_KT * W_TILE_B;

        const int tn = t + grid;
        const char* Anext = nullptr;
        const char* Wnext = nullptr;
        if (tn < N_TILES) {
            int group2 = tn / (GM * NUM_NT);
            int within2 = tn % (GM * NUM_NT);
            Anext = gA + (size_t)(group2 * GM + (within2 % GM)) * NUM_KT * A_TILE_B;
            Wnext = gW + (size_t)(within2 / GM) * NUM_KT * W_TILE_B;
        }

        if (first) {
            if (lane == 0 && warp < STAGES) fill(Abase, Wbase, warp);
            first = false;
        }

        float acc_s[4][4][4], acc_l[4][4][4];
        #pragma unroll
        for (int a = 0; a < 4; a++)
            #pragma unroll
            for (int b = 0; b < 4; b++)
                #pragma unroll
                for (int c = 0; c < 4; c++) { acc_s[a][b][c] = 0.f; acc_l[a][b][c] = 0.f; }

        auto do_mma = [&](int buf) {
            #pragma unroll
            for (int mf = 0; mf < 4; mf++)
                #pragma unroll
                for (int nf = 0; nf < 4; nf++) {
                    const int g = nf >> 1, sel = nf & 1;
                    mma16816(acc_s[mf][nf], afr[buf][mf], bkf[buf][g][sel], bkf[buf][g][sel + 2]);
                    mma16816(acc_l[mf][nf], afr[buf][mf], bmf[buf][g][sel], bmf[buf][g][sel + 2]);
                }
        };

        // tile start: wait half0 of stage 0, load kk0 frags
        mbar_wait(sb + 0, 0);
        load_frags(0, stg0, 0);

        for (int ks = 0; ks < NITER; ks++) {
            const int cur = ks & 1;
            const uint32_t st = cur ? stg1 : stg0;
            const uint32_t p = (ks >> 1) & 1;

            #pragma unroll
            for (int kk = 0; kk < 8; kk++) {
                if (kk < 7) {
                    // before first read of subtile 1 (the kk==4 frags, loaded at kk==3)
                    if (kk == 3) mbar_wait(sb + cur * 32 + 8, p);
                    load_frags((kk + 1) & 1, st, kk + 1);
                    if (kk == 6 && lane == 0) mbar_arrive(sb + cur * 32 + 16);
                } else {
                    if (warp == ((ks + 2) & 7) && lane == 0) {
                        if (ks + 2 < NITER)      fill(Abase, Wbase, ks + 2);
                        else if (Anext)          fill(Anext, Wnext, ks + 2 - NITER);
                    }
                    if (ks + 1 < NITER) {
                        const int nxt = (ks + 1) & 1;
                        // only half0 of next stage needed here
                        mbar_wait(sb + nxt * 32, ((ks + 1) >> 1) & 1);
                        load_frags(0, nxt ? stg1 : stg0, 0);
                    }
                }
                do_mma(kk & 1);
            }
        }

        // ---- register epilogue: gate/bias hoisted ----
        const int r0base = m_base + wm * 64 + (lane >> 2);
        const int cbase  = n_base + wn * 32 + (lane & 3) * 2;
        float2 gt[4], bs[4];
        #pragma unroll
        for (int nf = 0; nf < 4; nf++) {
            gt[nf] = __ldg(reinterpret_cast<const float2*>(gate + cbase + nf * 8));
            bs[nf] = __ldg(reinterpret_cast<const float2*>(bias + cbase + nf * 8));
        }
        #pragma unroll
        for (int mf = 0; mf < 4; mf++) {
            const int r0 = r0base + mf * 16;
            #pragma unroll
            for (int nf = 0; nf < 4; nf++) {
                const int c = cbase + nf * 8;
                float s0 = acc_s[mf][nf][0] * scale;
                float s1 = acc_s[mf][nf][1] * scale;
                float s2 = acc_s[mf][nf][2] * scale;
                float s3 = acc_s[mf][nf][3] * scale;
                float v0 = fmaf(fmaxf(s0 - gt[nf].x, 0.f), acc_l[mf][nf][0], bs[nf].x);
                float v1 = fmaf(fmaxf(s1 - gt[nf].y, 0.f), acc_l[mf][nf][1], bs[nf].y);
                float v2 = fmaf(fmaxf(s2 - gt[nf].x, 0.f), acc_l[mf][nf][2], bs[nf].x);
                float v3 = fmaf(fmaxf(s3 - gt[nf].y, 0.f), acc_l[mf][nf][3], bs[nf].y);
                size_t o0 = (size_t)r0 * D_OUT + c;
                size_t o1 = (size_t)(r0 + 8) * D_OUT + c;
                *reinterpret_cast<float2*>(o_final + o0) = make_float2(v0, v1);
                *reinterpret_cast<float2*>(o_final + o1) = make_float2(v2, v3);
                if (o_scores) {
                    *reinterpret_cast<float2*>(o_scores + o0) = make_float2(s0, s1);
                    *reinterpret_cast<float2*>(o_scores + o1) = make_float2(s2, s3);
                }
                if (o_output) {
                    *reinterpret_cast<float2*>(o_output + o0) = make_float2(v0, v1);
                    *reinterpret_cast<float2*>(o_output + o1) = make_float2(v2, v3);
                }
            }
        }
    }
}

// ---------------------------------------------------------------------------
extern "C" void kernel_launch(void* const* d_in, const int* in_sizes, int n_in,
                              void* d_out, int out_size) {
    const float* x     = (const float*)d_in[0];
    const float* mu    = (const float*)d_in[1];
    const float* sigma = (const float*)d_in[2];
    const float* gate  = (const float*)d_in[3];
    const float* bias  = (const float*)d_in[4];

    char *gA, *gW;
    cudaGetSymbolAddress((void**)&gA, g_xh);
    cudaGetSymbolAddress((void**)&gW, g_wh);

    const size_t n = (size_t)N_TOK * D_OUT;
    float* out = (float*)d_out;
    float* o_final  = out;
    float* o_scores = nullptr;
    float* o_output = nullptr;
    if ((size_t)out_size >= 3 * n)      { o_scores = out + n; o_output = out + 2 * n; }
    else if ((size_t)out_size >= 2 * n) { o_scores = out + n; }

    prep_all<<<PREP_XB + PREP_WB, 256>>>(x, mu, sigma, gA, gW);

    int sms = 148;
    cudaDeviceGetAttribute(&sms, cudaDevAttrMultiProcessorCount, 0);
    if (sms < 1) sms = 148;
    if (sms > N_TILES) sms = N_TILES;

    cudaFuncSetAttribute(sbl_gemm_pers,
                         cudaFuncAttributeMaxDynamicSharedMemorySize, SMEM_BYTES);
    sbl_gemm_pers<<<sms, THREADS, SMEM_BYTES>>>(gA, gW, gate, bias,
                                                o_final, o_scores, o_output);
}

// round 16
// speedup vs baseline: 1.0441x; 1.0441x over previous
#include <cuda_runtime.h>
#include <cuda_fp16.h>
#include <cstdint>

// Problem dims (fixed)
#define N_TOK   8192
#define D_IN    2048
#define D_OUT   8192

// Tiling
#define BM      128
#define BN      128
#define BK      128
#define NITER   (D_IN / BK)          // 16
#define STAGES  2
#define THREADS 256

#define A_TILE_B  32768
#define W_TILE_B  65536
#define STG_B     (A_TILE_B + W_TILE_B)      // 98304
#define SMEM_BYTES (1024 + STAGES * STG_B)   // 197632

#define NUM_MT  (N_TOK / BM)         // 64
#define NUM_NT  (D_OUT / BN)         // 64
#define NUM_KT  (D_IN / BK)          // 16
#define N_TILES (NUM_MT * NUM_NT)    // 4096

__device__ __align__(1024) char g_xh[(size_t)NUM_MT * NUM_KT * A_TILE_B];
__device__ __align__(1024) char g_wh[(size_t)NUM_NT * NUM_KT * W_TILE_B];

__device__ __forceinline__ uint32_t smem_u32(const void* p) {
    uint32_t a;
    asm("{ .reg .u64 t; cvta.to.shared.u64 t, %1; cvt.u32.u64 %0, t; }" : "=r"(a) : "l"(p));
    return a;
}
__device__ __forceinline__ uint32_t swz(uint32_t off) {
    return off ^ ((off >> 3) & 0x70);
}
__device__ __forceinline__ void ldsm4(uint32_t* r, uint32_t addr) {
    asm volatile("ldmatrix.sync.aligned.m8n8.x4.shared.b16 {%0,%1,%2,%3}, [%4];"
                 : "=r"(r[0]), "=r"(r[1]), "=r"(r[2]), "=r"(r[3]) : "r"(addr));
}
__device__ __forceinline__ void mma16816(float* c, const uint32_t* a,
                                         uint32_t b0, uint32_t b1) {
    asm volatile(
        "mma.sync.aligned.m16n8k16.row.col.f32.f16.f16.f32 "
        "{%0,%1,%2,%3}, {%4,%5,%6,%7}, {%8,%9}, {%0,%1,%2,%3};"
        : "+f"(c[0]), "+f"(c[1]), "+f"(c[2]), "+f"(c[3])
        : "r"(a[0]), "r"(a[1]), "r"(a[2]), "r"(a[3]), "r"(b0), "r"(b1));
}
__device__ __forceinline__ void mbar_init(uint32_t a, uint32_t cnt) {
    asm volatile("mbarrier.init.shared.b64 [%0], %1;" :: "r"(a), "r"(cnt) : "memory");
}
__device__ __forceinline__ void mbar_arrive(uint32_t a) {
    asm volatile("mbarrier.arrive.shared.b64 _, [%0];" :: "r"(a) : "memory");
}
__device__ __forceinline__ void mbar_expect_tx(uint32_t a, uint32_t bytes) {
    asm volatile("mbarrier.arrive.expect_tx.shared.b64 _, [%0], %1;"
                 :: "r"(a), "r"(bytes) : "memory");
}
// acquire variant: consumer waits (orders subsequent ldsm reads)
__device__ __forceinline__ void mbar_wait(uint32_t a, uint32_t parity) {
    asm volatile(
        "{\n\t.reg .pred P;\n\t"
        "WL_%=:\n\t"
        "mbarrier.try_wait.parity.acquire.cta.shared::cta.b64 P, [%0], %1, 0x989680;\n\t"
        "@P bra.uni WD_%=;\n\t"
        "bra.uni WL_%=;\n\t"
        "WD_%=:\n\t}"
        :: "r"(a), "r"(parity) : "memory");
}
// relaxed variant: producer empty-wait only (post-wait accesses are async-proxy)
__device__ __forceinline__ void mbar_wait_relaxed(uint32_t a, uint32_t parity) {
    asm volatile(
        "{\n\t.reg .pred P;\n\t"
        "WL_%=:\n\t"
        "mbarrier.try_wait.parity.relaxed.cta.shared::cta.b64 P, [%0], %1, 0x989680;\n\t"
        "@P bra.uni WD_%=;\n\t"
        "bra.uni WL_%=;\n\t"
        "WD_%=:\n\t}"
        :: "r"(a), "r"(parity) : "memory");
}
__device__ __forceinline__ void bulk_ld(uint32_t sdst, const void* gsrc,
                                        uint32_t bytes, uint32_t mbar) {
    asm volatile(
        "cp.async.bulk.shared::cluster.global.mbarrier::complete_tx::bytes "
        "[%0], [%1], %2, [%3];"
        :: "r"(sdst), "l"(gsrc), "r"(bytes), "r"(mbar) : "memory");
}

// ---------------------------------------------------------------------------
// Fused prep (verified mappings)
// ---------------------------------------------------------------------------
#define PREP_XB   2048
#define PREP_WB   4096
__global__ void prep_all(const float* __restrict__ x,
                         const float* __restrict__ mu,
                         const float* __restrict__ sigma,
                         char* __restrict__ dx, char* __restrict__ dw) {
    if (blockIdx.x < PREP_XB) {
        const int total = NUM_MT * 32 * 1024;
        int id = blockIdx.x * blockDim.x + threadIdx.x;
        int stride = PREP_XB * blockDim.x;
        for (; id < total; id += stride) {
            int t = id >> 10;
            uint32_t w = (id & 1023) * 16;
            uint32_t u = swz(w);
            int r = u >> 7, c = (u >> 4) & 7;
            int mt = t >> 5, kt = t & 31;
            const float* src = x + (size_t)(mt * 128 + r) * D_IN + kt * 64 + c * 8;
            float4 a = *reinterpret_cast<const float4*>(src);
            float4 b = *reinterpret_cast<const float4*>(src + 4);
            __half o[8] = { __float2half_rn(a.x), __float2half_rn(a.y),
                            __float2half_rn(a.z), __float2half_rn(a.w),
                            __float2half_rn(b.x), __float2half_rn(b.y),
                            __float2half_rn(b.z), __float2half_rn(b.w) };
            *reinterpret_cast<uint4*>(dx + (size_t)id * 16) = *reinterpret_cast<uint4*>(o);
        }
    } else {
        const int total = NUM_NT * 32 * 1024;
        int id = (blockIdx.x - PREP_XB) * blockDim.x + threadIdx.x;
        int stride = PREP_WB * blockDim.x;
        for (; id < total; id += stride) {
            int t = id >> 10;
            uint32_t w = (id & 1023) * 16;
            uint32_t u = swz(w);
            int r = u >> 7, c = (u >> 4) & 7;
            int nt = t >> 5;
            int kt64 = t & 31;
            int kt128 = kt64 >> 1, kh = kt64 & 1;
            const size_t so = (size_t)(nt * 128 + r) * D_IN + kt64 * 64 + c * 8;
            float4 a = *reinterpret_cast<const float4*>(mu + so);
            float4 b = *reinterpret_cast<const float4*>(mu + so + 4);
            float4 sa = *reinterpret_cast<const float4*>(sigma + so);
            float4 sb = *reinterpret_cast<const float4*>(sigma + so + 4);
            float m[8] = { a.x, a.y, a.z, a.w, b.x, b.y, b.z, b.w };
            float sg[8] = { sa.x, sa.y, sa.z, sa.w, sb.x, sb.y, sb.z, sb.w };
            __half ok[8], om[8];
            #pragma unroll
            for (int q = 0; q < 8; q++) {
                float sp = (sg[q] > 20.f) ? sg[q] : log1pf(expf(sg[q]));
                ok[q] = __float2half_rn(m[q] * sp);
                om[q] = __float2half_rn(m[q]);
            }
            char* tb = dw + ((size_t)nt * NUM_KT + kt128) * W_TILE_B + kh * 16384;
            *reinterpret_cast<uint4*>(tb + w)         = *reinterpret_cast<uint4*>(ok);
            *reinterpret_cast<uint4*>(tb + 32768 + w) = *reinterpret_cast<uint4*>(om);
        }
    }
}

// ---------------------------------------------------------------------------
// Persistent fused dual GEMM (R14 layout — best known): BK=128, 2-stage ring,
// rotating filler (relaxed empty-wait), early empty-arrive at kk==6,
// cross-stage kk0 fragment prefetch at kk==7.
// ---------------------------------------------------------------------------
__global__ void __launch_bounds__(THREADS, 1)
sbl_gemm_pers(const char* __restrict__ gA,
              const char* __restrict__ gW,
              const float* __restrict__ gate,
              const float* __restrict__ bias,
              float* __restrict__ o_final,
              float* __restrict__ o_scores,
              float* __restrict__ o_output) {
    extern __shared__ char smem[];
    const uint32_t sb = smem_u32(smem);
    const int tid = threadIdx.x;
    const int warp = tid >> 5;
    const int lane = tid & 31;
    const int wm = warp >> 2;
    const int wn = warp & 3;

    if (tid == 0) {
        #pragma unroll
        for (int s = 0; s < STAGES; s++) {
            mbar_init(sb + s * 16, 1);       // full
            mbar_init(sb + s * 16 + 8, 8);   // empty
        }
    }
    __syncthreads();

    const uint32_t stg0 = sb + 1024;
    const uint32_t stg1 = sb + 1024 + STG_B;

    const int lr = lane & 15;
    const int lc = lane >> 4;
    uint32_t abase[4], bkb[2], bmb[2];
    #pragma unroll
    for (int mf = 0; mf < 4; mf++)
        abase[mf] = swz((wm * 64 + mf * 16 + lr) * 128 + lc * 16);
    #pragma unroll
    for (int g = 0; g < 2; g++) {
        uint32_t o = swz((wn * 32 + g * 16 + lr) * 128 + lc * 16);
        bkb[g] = A_TILE_B + o;
        bmb[g] = A_TILE_B + 32768 + o;
    }

    uint32_t afr[2][4][4], bkf[2][2][4], bmf[2][2][4];

    auto load_frags = [&](int buf, uint32_t st, int kk) {
        const uint32_t kh = (uint32_t)(kk >> 2) << 14;
        const uint32_t kx = (uint32_t)(kk & 3) << 5;
        #pragma unroll
        for (int mf = 0; mf < 4; mf++)
            ldsm4(afr[buf][mf], st + kh + (abase[mf] ^ kx));
        #pragma unroll
        for (int g = 0; g < 2; g++) {
            ldsm4(bkf[buf][g], st + kh + (bkb[g] ^ kx));
            ldsm4(bmf[buf][g], st + kh + (bmb[g] ^ kx));
        }
    };

    auto fill = [&](const char* Ab, const char* Wb, int kt) {
        const int s = kt & 1;
        mbar_wait_relaxed(sb + s * 16 + 8, ((kt >> 1) & 1) ^ 1);   // producer: relaxed OK
        const uint32_t full = sb + s * 16;
        mbar_expect_tx(full, STG_B);
        const uint32_t st = s ? stg1 : stg0;
        bulk_ld(st, Ab + (size_t)kt * A_TILE_B, A_TILE_B, full);
        bulk_ld(st + A_TILE_B, Wb + (size_t)kt * W_TILE_B, W_TILE_B, full);
    };

    const int grid = gridDim.x;
    const float scale = 0.022097086912079608f;   // 1/sqrt(2048)

    bool first = true;
    for (int t = blockIdx.x; t < N_TILES; t += grid) {
        const int GM = 8;
        int group = t / (GM * NUM_NT);
        int within = t % (GM * NUM_NT);
        const int m_idx = group * GM + (within % GM);
        const int n_idx = within / GM;
        const int m_base = m_idx * BM;
        const int n_base = n_idx * BN;
        const char* Abase = gA + (size_t)m_idx * NUM_KT * A_TILE_B;
        const char* Wbase = gW + (size_t)n_idx * NUM_KT * W_TILE_B;

        const int tn = t + grid;
        const char* Anext = nullptr;
        const char* Wnext = nullptr;
        if (tn < N_TILES) {
            int group2 = tn / (GM * NUM_NT);
            int within2 = tn % (GM * NUM_NT);
            Anext = gA + (size_t)(group2 * GM + (within2 % GM)) * NUM_KT * A_TILE_B;
            Wnext = gW + (size_t)(within2 / GM) * NUM_KT * W_TILE_B;
        }

        if (first) {
            if (lane == 0 && warp < STAGES) fill(Abase, Wbase, warp);
            first = false;
        }

        float acc_s[4][4][4], acc_l[4][4][4];
        #pragma unroll
        for (int a = 0; a < 4; a++)
            #pragma unroll
            for (int b = 0; b < 4; b++)
                #pragma unroll
                for (int c = 0; c < 4; c++) { acc_s[a][b][c] = 0.f; acc_l[a][b][c] = 0.f; }

        auto do_mma = [&](int buf) {
            #pragma unroll
            for (int mf = 0; mf < 4; mf++)
                #pragma unroll
                for (int nf = 0; nf < 4; nf++) {
                    const int g = nf >> 1, sel = nf & 1;
                    mma16816(acc_s[mf][nf], afr[buf][mf], bkf[buf][g][sel], bkf[buf][g][sel + 2]);
                    mma16816(acc_l[mf][nf], afr[buf][mf], bmf[buf][g][sel], bmf[buf][g][sel + 2]);
                }
        };

        mbar_wait(sb + 0, 0);
        load_frags(0, stg0, 0);

        for (int ks = 0; ks < NITER; ks++) {
            const int cur = ks & 1;
            const uint32_t st = cur ? stg1 : stg0;

            #pragma unroll
            for (int kk = 0; kk < 8; kk++) {
                if (kk < 7) {
                    load_frags((kk + 1) & 1, st, kk + 1);
                    if (kk == 6 && lane == 0) mbar_arrive(sb + cur * 16 + 8);
                } else {
                    if (warp == ((ks + 2) & 7) && lane == 0) {
                        if (ks + 2 < NITER)      fill(Abase, Wbase, ks + 2);
                        else if (Anext)          fill(Anext, Wnext, ks + 2 - NITER);
                    }
                    if (ks + 1 < NITER) {
                        const int nxt = (ks + 1) & 1;
                        mbar_wait(sb + nxt * 16, ((ks + 1) >> 1) & 1);
                        load_frags(0, nxt ? stg1 : stg0, 0);
                    }
                }
                do_mma(kk & 1);
            }
        }

        // ---- register epilogue: gate/bias hoisted ----
        const int r0base = m_base + wm * 64 + (lane >> 2);
        const int cbase  = n_base + wn * 32 + (lane & 3) * 2;
        float2 gt[4], bs[4];
        #pragma unroll
        for (int nf = 0; nf < 4; nf++) {
            gt[nf] = __ldg(reinterpret_cast<const float2*>(gate + cbase + nf * 8));
            bs[nf] = __ldg(reinterpret_cast<const float2*>(bias + cbase + nf * 8));
        }
        #pragma unroll
        for (int mf = 0; mf < 4; mf++) {
            const int r0 = r0base + mf * 16;
            #pragma unroll
            for (int nf = 0; nf < 4; nf++) {
                const int c = cbase + nf * 8;
                float s0 = acc_s[mf][nf][0] * scale;
                float s1 = acc_s[mf][nf][1] * scale;
                float s2 = acc_s[mf][nf][2] * scale;
                float s3 = acc_s[mf][nf][3] * scale;
                float v0 = fmaf(fmaxf(s0 - gt[nf].x, 0.f), acc_l[mf][nf][0], bs[nf].x);
                float v1 = fmaf(fmaxf(s1 - gt[nf].y, 0.f), acc_l[mf][nf][1], bs[nf].y);
                float v2 = fmaf(fmaxf(s2 - gt[nf].x, 0.f), acc_l[mf][nf][2], bs[nf].x);
                float v3 = fmaf(fmaxf(s3 - gt[nf].y, 0.f), acc_l[mf][nf][3], bs[nf].y);
                size_t o0 = (size_t)r0 * D_OUT + c;
                size_t o1 = (size_t)(r0 + 8) * D_OUT + c;
                *reinterpret_cast<float2*>(o_final + o0) = make_float2(v0, v1);
                *reinterpret_cast<float2*>(o_final + o1) = make_float2(v2, v3);
                if (o_scores) {
                    *reinterpret_cast<float2*>(o_scores + o0) = make_float2(s0, s1);
                    *reinterpret_cast<float2*>(o_scores + o1) = make_float2(s2, s3);
                }
                if (o_output) {
                    *reinterpret_cast<float2*>(o_output + o0) = make_float2(v0, v1);
                    *reinterpret_cast<float2*>(o_output + o1) = make_float2(v2, v3);
                }
            }
        }
    }
}

// ---------------------------------------------------------------------------
extern "C" void kernel_launch(void* const* d_in, const int* in_sizes, int n_in,
                              void* d_out, int out_size) {
    const float* x     = (const float*)d_in[0];
    const float* mu    = (const float*)d_in[1];
    const float* sigma = (const float*)d_in[2];
    const float* gate  = (const float*)d_in[3];
    const float* bias  = (const float*)d_in[4];

    char *gA, *gW;
    cudaGetSymbolAddress((void**)&gA, g_xh);
    cudaGetSymbolAddress((void**)&gW, g_wh);

    const size_t n = (size_t)N_TOK * D_OUT;
    float* out = (float*)d_out;
    float* o_final  = out;
    float* o_scores = nullptr;
    float* o_output = nullptr;
    if ((size_t)out_size >= 3 * n)      { o_scores = out + n; o_output = out + 2 * n; }
    else if ((size_t)out_size >= 2 * n) { o_scores = out + n; }

    prep_all<<<PREP_XB + PREP_WB, 256>>>(x, mu, sigma, gA, gW);

    int sms = 148;
    cudaDeviceGetAttribute(&sms, cudaDevAttrMultiProcessorCount, 0);
    if (sms < 1) sms = 148;
    if (sms > N_TILES) sms = N_TILES;

    cudaFuncSetAttribute(sbl_gemm_pers,
                         cudaFuncAttributeMaxDynamicSharedMemorySize, SMEM_BYTES);
    sbl_gemm_pers<<<sms, THREADS, SMEM_BYTES>>>(gA, gW, gate, bias,
                                                o_final, o_scores, o_output);
}